// round 1
// baseline (speedup 1.0000x reference)
#include <cuda_runtime.h>
#include <math.h>

#define BB 256
#define NN 2048
#define NSUM 22   // M(6 sym), C(9), mw(3), yw(3), wsum(1)

// scratch (no allocations allowed)
__device__ float g_sums[BB * NSUM];
__device__ float g_sq[BB];

// ---------------------------------------------------------------------------
// Stage 1: per-batch weighted sums over N. One block per batch.
// sums layout: [0..5]=M(00,01,02,11,12,22), [6..14]=C[i][j] (row-major, i=m idx),
//              [15..17]=mw, [18..20]=yw, [21]=wsum
// ---------------------------------------------------------------------------
__global__ __launch_bounds__(256) void reduce_kernel(
    const float* __restrict__ src, const float* __restrict__ trg,
    const float* __restrict__ w)
{
    int b = blockIdx.x;
    const float* m0 = src + (size_t)b * 4 * NN;
    const float* m1 = m0 + NN;
    const float* m2 = m0 + 2 * NN;
    const float* y0 = trg + (size_t)b * 4 * NN;
    const float* y1 = y0 + NN;
    const float* y2 = y0 + 2 * NN;
    const float* wp = w + (size_t)b * NN;

    float acc[NSUM];
#pragma unroll
    for (int k = 0; k < NSUM; k++) acc[k] = 0.f;

    for (int n = threadIdx.x; n < NN; n += blockDim.x) {
        float wv = __ldg(wp + n);
        float a0 = __ldg(m0 + n), a1 = __ldg(m1 + n), a2 = __ldg(m2 + n);
        float c0 = __ldg(y0 + n), c1 = __ldg(y1 + n), c2 = __ldg(y2 + n);
        float w0 = wv * a0, w1 = wv * a1, w2 = wv * a2;
        acc[0]  += w0 * a0; acc[1]  += w0 * a1; acc[2]  += w0 * a2;
        acc[3]  += w1 * a1; acc[4]  += w1 * a2; acc[5]  += w2 * a2;
        acc[6]  += w0 * c0; acc[7]  += w0 * c1; acc[8]  += w0 * c2;
        acc[9]  += w1 * c0; acc[10] += w1 * c1; acc[11] += w1 * c2;
        acc[12] += w2 * c0; acc[13] += w2 * c1; acc[14] += w2 * c2;
        acc[15] += w0;      acc[16] += w1;      acc[17] += w2;
        acc[18] += wv * c0; acc[19] += wv * c1; acc[20] += wv * c2;
        acc[21] += wv;
    }

    // warp reduce all 22
#pragma unroll
    for (int k = 0; k < NSUM; k++)
#pragma unroll
        for (int off = 16; off > 0; off >>= 1)
            acc[k] += __shfl_xor_sync(0xFFFFFFFFu, acc[k], off);

    __shared__ float sm[8][NSUM];
    int wid = threadIdx.x >> 5, lane = threadIdx.x & 31;
    if (lane == 0)
#pragma unroll
        for (int k = 0; k < NSUM; k++) sm[wid][k] = acc[k];
    __syncthreads();
    if (threadIdx.x < NSUM) {
        float s = 0.f;
        int nw = blockDim.x >> 5;
        for (int ww = 0; ww < nw; ww++) s += sm[ww][threadIdx.x];
        g_sums[b * NSUM + threadIdx.x] = s;
    }
}

// ---------------------------------------------------------------------------
// Stage 2: pose solve. One thread per batch (fp64 Jacobi SVD of 3x3).
// Writes T_trg_src (B,4,4) to out[0 .. 4095].
// ---------------------------------------------------------------------------
__global__ __launch_bounds__(256) void pose_kernel(
    const float* __restrict__ tsv_in, float* __restrict__ tout)
{
    int b = threadIdx.x;
    if (b >= BB) return;
    const float* s = g_sums + b * NSUM;

    double C[3][3], mw[3], yw[3];
#pragma unroll
    for (int i = 0; i < 3; i++)
#pragma unroll
        for (int j = 0; j < 3; j++) C[i][j] = (double)s[6 + 3 * i + j];
#pragma unroll
    for (int i = 0; i < 3; i++) { mw[i] = (double)s[15 + i]; yw[i] = (double)s[18 + i]; }
    double ws = (double)s[21];
    double inv_ws = 1.0 / ws;

    // H = C^T - yw mw^T / ws
    double H[3][3];
#pragma unroll
    for (int i = 0; i < 3; i++)
#pragma unroll
        for (int j = 0; j < 3; j++)
            H[i][j] = C[j][i] - yw[i] * mw[j] * inv_ws;

    double mum[3], muy[3];
#pragma unroll
    for (int i = 0; i < 3; i++) { mum[i] = mw[i] * inv_ws; muy[i] = yw[i] * inv_ws; }

    // A = H^T H (symmetric)
    double A[3][3];
#pragma unroll
    for (int i = 0; i < 3; i++)
#pragma unroll
        for (int j = 0; j < 3; j++) {
            double t = 0.0;
#pragma unroll
            for (int k = 0; k < 3; k++) t += H[k][i] * H[k][j];
            A[i][j] = t;
        }

    // Jacobi eigendecomposition: A = V L V^T
    double V[3][3] = {{1,0,0},{0,1,0},{0,0,1}};
    for (int sweep = 0; sweep < 8; sweep++) {
#pragma unroll
        for (int r = 0; r < 3; r++) {
            int p = (r == 0) ? 0 : (r == 1) ? 0 : 1;
            int q = (r == 0) ? 1 : 2;
            double apq = A[p][q];
            if (fabs(apq) < 1e-300) continue;
            double app = A[p][p], aqq = A[q][q];
            double tau = (aqq - app) / (2.0 * apq);
            double t = ((tau >= 0.0) ? 1.0 : -1.0) / (fabs(tau) + sqrt(1.0 + tau * tau));
            double c = 1.0 / sqrt(1.0 + t * t);
            double sn = t * c;
            double tau2 = sn / (1.0 + c);
            A[p][p] = app - t * apq;
            A[q][q] = aqq + t * apq;
            A[p][q] = 0.0; A[q][p] = 0.0;
            int k = 3 - p - q;  // remaining index
            double akp = A[k][p], akq = A[k][q];
            A[k][p] = akp - sn * (akq + tau2 * akp);
            A[p][k] = A[k][p];
            A[k][q] = akq + sn * (akp - tau2 * akq);
            A[q][k] = A[k][q];
#pragma unroll
            for (int kk = 0; kk < 3; kk++) {
                double vkp = V[kk][p], vkq = V[kk][q];
                V[kk][p] = vkp - sn * (vkq + tau2 * vkp);
                V[kk][q] = vkq + sn * (vkp - tau2 * vkq);
            }
        }
    }

    double lam[3] = {A[0][0], A[1][1], A[2][2]};
    // sort descending (columns of V follow)
#pragma unroll
    for (int i = 0; i < 2; i++)
#pragma unroll
        for (int j = 0; j < 2 - i; j++) {
            if (lam[j] < lam[j + 1]) {
                double tl = lam[j]; lam[j] = lam[j + 1]; lam[j + 1] = tl;
#pragma unroll
                for (int k = 0; k < 3; k++) {
                    double tv = V[k][j]; V[k][j] = V[k][j + 1]; V[k][j + 1] = tv;
                }
            }
        }

    double sv[3];
#pragma unroll
    for (int k = 0; k < 3; k++) sv[k] = sqrt(fmax(lam[k], 0.0));

    // U columns: u_k = H v_k / s_k
    double U[3][3];
#pragma unroll
    for (int k = 0; k < 3; k++) {
        double inv_s = 1.0 / fmax(sv[k], 1e-30);
#pragma unroll
        for (int i = 0; i < 3; i++) {
            double t = 0.0;
#pragma unroll
            for (int j = 0; j < 3; j++) t += H[i][j] * V[j][k];
            U[i][k] = t * inv_s;
        }
    }

    double detH = H[0][0] * (H[1][1] * H[2][2] - H[1][2] * H[2][1])
                - H[0][1] * (H[1][0] * H[2][2] - H[1][2] * H[2][0])
                + H[0][2] * (H[1][0] * H[2][1] - H[1][1] * H[2][0]);
    double d3 = (detH >= 0.0) ? 1.0 : -1.0;

    // R = U diag(1,1,d3) V^T
    double R[3][3];
#pragma unroll
    for (int i = 0; i < 3; i++)
#pragma unroll
        for (int j = 0; j < 3; j++)
            R[i][j] = U[i][0] * V[j][0] + U[i][1] * V[j][1] + d3 * U[i][2] * V[j][2];

    // t = R mu_m - mu_y
    double tt[3];
#pragma unroll
    for (int i = 0; i < 3; i++)
        tt[i] = R[i][0] * mum[0] + R[i][1] * mum[1] + R[i][2] * mum[2] - muy[i];

    // T = [[R, -t], [0 0 0 1]]
    double T[4][4];
#pragma unroll
    for (int i = 0; i < 3; i++) {
#pragma unroll
        for (int j = 0; j < 3; j++) T[i][j] = R[i][j];
        T[i][3] = -tt[i];
    }
    T[3][0] = 0.0; T[3][1] = 0.0; T[3][2] = 0.0; T[3][3] = 1.0;

    // T_s_v and its inverse
    double Tsv[4][4];
#pragma unroll
    for (int i = 0; i < 4; i++)
#pragma unroll
        for (int j = 0; j < 4; j++) Tsv[i][j] = (double)tsv_in[i * 4 + j];

    double Tinv[4][4];
#pragma unroll
    for (int i = 0; i < 3; i++) {
#pragma unroll
        for (int j = 0; j < 3; j++) Tinv[i][j] = Tsv[j][i];  // Rv^T
        Tinv[i][3] = -(Tsv[0][i] * Tsv[0][3] + Tsv[1][i] * Tsv[1][3] + Tsv[2][i] * Tsv[2][3]);
    }
    Tinv[3][0] = 0.0; Tinv[3][1] = 0.0; Tinv[3][2] = 0.0; Tinv[3][3] = 1.0;

    // out = Tinv * T * Tsv
    double M1[4][4];
#pragma unroll
    for (int i = 0; i < 4; i++)
#pragma unroll
        for (int j = 0; j < 4; j++) {
            double t = 0.0;
#pragma unroll
            for (int k = 0; k < 4; k++) t += Tinv[i][k] * T[k][j];
            M1[i][j] = t;
        }
    float* ob = tout + b * 16;
#pragma unroll
    for (int i = 0; i < 4; i++)
#pragma unroll
        for (int j = 0; j < 4; j++) {
            double t = 0.0;
#pragma unroll
            for (int k = 0; k < 4; k++) t += M1[i][k] * Tsv[k][j];
            ob[i * 4 + j] = (float)t;
        }
}

// ---------------------------------------------------------------------------
// Stage 3: fill unscaled Q (B,13,13) into d_out region + per-batch sum-of-squares.
// One block (256 thr) per batch; threads 0..168 each own one entry.
// ---------------------------------------------------------------------------
__device__ __forceinline__ int sym6(int a, int c) {
    if (a > c) { int t = a; a = c; c = t; }
    return (a == 0) ? c : (a == 1) ? (2 + c) : 5;
}

__global__ __launch_bounds__(256) void q_kernel(float* __restrict__ qout)
{
    int b = blockIdx.x;
    int t = threadIdx.x;
    __shared__ float ss[NSUM];
    if (t < NSUM) ss[t] = g_sums[b * NSUM + t];
    __syncthreads();

    float val = 0.f;
    if (t < 169) {
        int i = t / 13, j = t % 13;
        if (i == 0 && j == 0) {
            val = 0.f;
        } else if (i == 0 && j <= 9) {
            int k = j - 1; val = -ss[6 + k];                 // ch = -C flat
        } else if (i == 0) {
            val = ss[18 + (j - 10)];                          // yw
        } else if (j == 0 && i <= 9) {
            int k = i - 1; val = -ss[6 + k];
        } else if (j == 0) {
            val = ss[18 + (i - 10)];
        } else if (i <= 9 && j <= 9) {
            int a = (i - 1) / 3, r = (i - 1) % 3;
            int bb = (j - 1) / 3, c = (j - 1) % 3;
            if (r == c) val = ss[sym6(a, bb)];                // kron(M, I3)
        } else if (i <= 9) {
            int a = (i - 1) / 3, r = (i - 1) % 3, c = j - 10;
            if (r == c) val = -ss[15 + a];                    // ct
        } else if (j <= 9) {
            int a = (j - 1) / 3, r = (j - 1) % 3, c = i - 10;
            if (r == c) val = -ss[15 + a];                    // ct^T
        } else {
            if (i == j) val = ss[21];                         // wsum * I3
        }
        qout[b * 169 + t] = val;
    }

    // block-reduce sum of squares (deterministic)
    float s2 = val * val;
#pragma unroll
    for (int off = 16; off > 0; off >>= 1)
        s2 += __shfl_xor_sync(0xFFFFFFFFu, s2, off);
    __shared__ float sm[8];
    int wid = t >> 5, lane = t & 31;
    if (lane == 0) sm[wid] = s2;
    __syncthreads();
    if (t == 0) {
        float tot = 0.f;
        for (int ww = 0; ww < 8; ww++) tot += sm[ww];
        g_sq[b] = tot;
    }
}

// ---------------------------------------------------------------------------
// Stage 4: global scale = ||Q||_F over whole tensor; Q /= scale in place.
// Single block, deterministic.
// ---------------------------------------------------------------------------
__global__ __launch_bounds__(1024) void scale_kernel(float* __restrict__ qout)
{
    int t = threadIdx.x;
    float v = (t < BB) ? g_sq[t] : 0.f;
#pragma unroll
    for (int off = 16; off > 0; off >>= 1)
        v += __shfl_xor_sync(0xFFFFFFFFu, v, off);
    __shared__ float sm[32];
    __shared__ float inv_scale;
    int wid = t >> 5, lane = t & 31;
    if (lane == 0) sm[wid] = v;
    __syncthreads();
    if (t == 0) {
        float tot = 0.f;
        for (int ww = 0; ww < 32; ww++) tot += sm[ww];
        inv_scale = 1.f / sqrtf(tot);
    }
    __syncthreads();
    float inv = inv_scale;
    const int total = BB * 169;
    for (int idx = t; idx < total; idx += 1024)
        qout[idx] *= inv;
}

// ---------------------------------------------------------------------------
extern "C" void kernel_launch(void* const* d_in, const int* in_sizes, int n_in,
                              void* d_out, int out_size)
{
    const float* src = (const float*)d_in[0];
    const float* trg = (const float*)d_in[1];
    const float* w   = (const float*)d_in[2];
    const float* tsv = (const float*)d_in[3];
    float* out  = (float*)d_out;
    float* tout = out;                 // (B,4,4) = 4096 floats
    float* qout = out + BB * 16;       // (B,13,13) = 43264 floats

    reduce_kernel<<<BB, 256>>>(src, trg, w);
    pose_kernel<<<1, 256>>>(tsv, tout);
    q_kernel<<<BB, 256>>>(qout);
    scale_kernel<<<1, 1024>>>(qout);
}

// round 2
// speedup vs baseline: 1.2588x; 1.2588x over previous
#include <cuda_runtime.h>
#include <math.h>

#define BB 256
#define NN 2048
#define NSUM 22   // M(6 sym), C(9), mw(3), yw(3), wsum(1)

// scratch (no allocations allowed)
__device__ float g_sums[BB * NSUM];
__device__ float g_inv_scale;

// ---------------------------------------------------------------------------
// Stage 1: per-batch weighted sums over N. One block per batch, float4 loads.
// sums layout: [0..5]=M(00,01,02,11,12,22), [6..14]=C[i][j] (row-major, i=m idx),
//              [15..17]=mw, [18..20]=yw, [21]=wsum
// ---------------------------------------------------------------------------
__global__ __launch_bounds__(256) void reduce_kernel(
    const float* __restrict__ src, const float* __restrict__ trg,
    const float* __restrict__ w)
{
    int b = blockIdx.x;
    const float4* m0 = (const float4*)(src + (size_t)b * 4 * NN);
    const float4* m1 = (const float4*)(src + (size_t)b * 4 * NN + NN);
    const float4* m2 = (const float4*)(src + (size_t)b * 4 * NN + 2 * NN);
    const float4* y0 = (const float4*)(trg + (size_t)b * 4 * NN);
    const float4* y1 = (const float4*)(trg + (size_t)b * 4 * NN + NN);
    const float4* y2 = (const float4*)(trg + (size_t)b * 4 * NN + 2 * NN);
    const float4* wp = (const float4*)(w + (size_t)b * NN);

    float acc[NSUM];
#pragma unroll
    for (int k = 0; k < NSUM; k++) acc[k] = 0.f;

    const int NV = NN / 4;  // 512 float4 per row
#pragma unroll 2
    for (int n = threadIdx.x; n < NV; n += 256) {
        float4 wv4 = __ldg(wp + n);
        float4 a04 = __ldg(m0 + n), a14 = __ldg(m1 + n), a24 = __ldg(m2 + n);
        float4 c04 = __ldg(y0 + n), c14 = __ldg(y1 + n), c24 = __ldg(y2 + n);
        const float* wvp = &wv4.x;
        const float* a0p = &a04.x; const float* a1p = &a14.x; const float* a2p = &a24.x;
        const float* c0p = &c04.x; const float* c1p = &c14.x; const float* c2p = &c24.x;
#pragma unroll
        for (int l = 0; l < 4; l++) {
            float wv = wvp[l];
            float a0 = a0p[l], a1 = a1p[l], a2 = a2p[l];
            float c0 = c0p[l], c1 = c1p[l], c2 = c2p[l];
            float w0 = wv * a0, w1 = wv * a1, w2 = wv * a2;
            acc[0]  += w0 * a0; acc[1]  += w0 * a1; acc[2]  += w0 * a2;
            acc[3]  += w1 * a1; acc[4]  += w1 * a2; acc[5]  += w2 * a2;
            acc[6]  += w0 * c0; acc[7]  += w0 * c1; acc[8]  += w0 * c2;
            acc[9]  += w1 * c0; acc[10] += w1 * c1; acc[11] += w1 * c2;
            acc[12] += w2 * c0; acc[13] += w2 * c1; acc[14] += w2 * c2;
            acc[15] += w0;      acc[16] += w1;      acc[17] += w2;
            acc[18] += wv * c0; acc[19] += wv * c1; acc[20] += wv * c2;
            acc[21] += wv;
        }
    }

    // warp reduce all 22
#pragma unroll
    for (int k = 0; k < NSUM; k++)
#pragma unroll
        for (int off = 16; off > 0; off >>= 1)
            acc[k] += __shfl_xor_sync(0xFFFFFFFFu, acc[k], off);

    __shared__ float sm[8][NSUM];
    int wid = threadIdx.x >> 5, lane = threadIdx.x & 31;
    if (lane == 0)
#pragma unroll
        for (int k = 0; k < NSUM; k++) sm[wid][k] = acc[k];
    __syncthreads();
    if (threadIdx.x < NSUM) {
        float s = 0.f;
#pragma unroll
        for (int ww = 0; ww < 8; ww++) s += sm[ww][threadIdx.x];
        g_sums[b * NSUM + threadIdx.x] = s;
    }
}

// ---------------------------------------------------------------------------
// Stage 2: pose solve + global Frobenius norm (fused).
// One thread per batch (fp64 Jacobi SVD of 3x3). Writes T_trg_src to tout.
// Also computes per-batch ||Q_b||^2 in closed form from the sums, block-reduces,
// and stores inv_scale = rsqrt(sum) to g_inv_scale.
// ---------------------------------------------------------------------------
__global__ __launch_bounds__(256) void pose_kernel(
    const float* __restrict__ tsv_in, float* __restrict__ tout)
{
    int b = threadIdx.x;
    const float* s = g_sums + b * NSUM;

    // ---- per-batch Q norm^2 (closed form, no Q materialization) ----
    float nq = 3.f * (s[0]*s[0] + s[3]*s[3] + s[5]*s[5])
             + 6.f * (s[1]*s[1] + s[2]*s[2] + s[4]*s[4]);
#pragma unroll
    for (int k = 6; k < 15; k++) nq += 2.f * s[k] * s[k];
#pragma unroll
    for (int k = 15; k < 18; k++) nq += 6.f * s[k] * s[k];
#pragma unroll
    for (int k = 18; k < 21; k++) nq += 2.f * s[k] * s[k];
    nq += 3.f * s[21] * s[21];

#pragma unroll
    for (int off = 16; off > 0; off >>= 1)
        nq += __shfl_xor_sync(0xFFFFFFFFu, nq, off);
    __shared__ float smq[8];
    int wid = threadIdx.x >> 5, lane = threadIdx.x & 31;
    if (lane == 0) smq[wid] = nq;
    __syncthreads();
    if (threadIdx.x == 0) {
        float tot = 0.f;
#pragma unroll
        for (int ww = 0; ww < 8; ww++) tot += smq[ww];
        g_inv_scale = rsqrtf(tot) * (1.f + 0.f);  // refine below
        // one Newton step for full-precision rsqrt
        float x = g_inv_scale;
        x = x * (1.5f - 0.5f * tot * x * x);
        g_inv_scale = x;
    }

    // ---- pose (fp64) ----
    double C[3][3], mw[3], yw[3];
#pragma unroll
    for (int i = 0; i < 3; i++)
#pragma unroll
        for (int j = 0; j < 3; j++) C[i][j] = (double)s[6 + 3 * i + j];
#pragma unroll
    for (int i = 0; i < 3; i++) { mw[i] = (double)s[15 + i]; yw[i] = (double)s[18 + i]; }
    double ws = (double)s[21];
    double inv_ws = 1.0 / ws;

    // H = C^T - yw mw^T / ws
    double H[3][3];
#pragma unroll
    for (int i = 0; i < 3; i++)
#pragma unroll
        for (int j = 0; j < 3; j++)
            H[i][j] = C[j][i] - yw[i] * mw[j] * inv_ws;

    double mum[3], muy[3];
#pragma unroll
    for (int i = 0; i < 3; i++) { mum[i] = mw[i] * inv_ws; muy[i] = yw[i] * inv_ws; }

    // A = H^T H (symmetric)
    double A[3][3];
#pragma unroll
    for (int i = 0; i < 3; i++)
#pragma unroll
        for (int j = 0; j < 3; j++) {
            double t = 0.0;
#pragma unroll
            for (int k = 0; k < 3; k++) t += H[k][i] * H[k][j];
            A[i][j] = t;
        }

    // Jacobi eigendecomposition: A = V L V^T  (6 sweeps, quadratic convergence)
    double V[3][3] = {{1,0,0},{0,1,0},{0,0,1}};
    for (int sweep = 0; sweep < 6; sweep++) {
#pragma unroll
        for (int r = 0; r < 3; r++) {
            int p = (r == 2) ? 1 : 0;
            int q = (r == 0) ? 1 : 2;
            double apq = A[p][q];
            if (fabs(apq) < 1e-300) continue;
            double app = A[p][p], aqq = A[q][q];
            double tau = (aqq - app) / (2.0 * apq);
            double t = ((tau >= 0.0) ? 1.0 : -1.0) / (fabs(tau) + sqrt(1.0 + tau * tau));
            double c = 1.0 / sqrt(1.0 + t * t);
            double sn = t * c;
            double tau2 = sn / (1.0 + c);
            A[p][p] = app - t * apq;
            A[q][q] = aqq + t * apq;
            A[p][q] = 0.0; A[q][p] = 0.0;
            int k = 3 - p - q;
            double akp = A[k][p], akq = A[k][q];
            A[k][p] = akp - sn * (akq + tau2 * akp);
            A[p][k] = A[k][p];
            A[k][q] = akq + sn * (akp - tau2 * akq);
            A[q][k] = A[k][q];
#pragma unroll
            for (int kk = 0; kk < 3; kk++) {
                double vkp = V[kk][p], vkq = V[kk][q];
                V[kk][p] = vkp - sn * (vkq + tau2 * vkp);
                V[kk][q] = vkq + sn * (vkp - tau2 * vkq);
            }
        }
    }

    double lam[3] = {A[0][0], A[1][1], A[2][2]};
#pragma unroll
    for (int i = 0; i < 2; i++)
#pragma unroll
        for (int j = 0; j < 2 - i; j++) {
            if (lam[j] < lam[j + 1]) {
                double tl = lam[j]; lam[j] = lam[j + 1]; lam[j + 1] = tl;
#pragma unroll
                for (int k = 0; k < 3; k++) {
                    double tv = V[k][j]; V[k][j] = V[k][j + 1]; V[k][j + 1] = tv;
                }
            }
        }

    double sv[3];
#pragma unroll
    for (int k = 0; k < 3; k++) sv[k] = sqrt(fmax(lam[k], 0.0));

    double U[3][3];
#pragma unroll
    for (int k = 0; k < 3; k++) {
        double inv_s = 1.0 / fmax(sv[k], 1e-30);
#pragma unroll
        for (int i = 0; i < 3; i++) {
            double t = 0.0;
#pragma unroll
            for (int j = 0; j < 3; j++) t += H[i][j] * V[j][k];
            U[i][k] = t * inv_s;
        }
    }

    double detH = H[0][0] * (H[1][1] * H[2][2] - H[1][2] * H[2][1])
                - H[0][1] * (H[1][0] * H[2][2] - H[1][2] * H[2][0])
                + H[0][2] * (H[1][0] * H[2][1] - H[1][1] * H[2][0]);
    double d3 = (detH >= 0.0) ? 1.0 : -1.0;

    double R[3][3];
#pragma unroll
    for (int i = 0; i < 3; i++)
#pragma unroll
        for (int j = 0; j < 3; j++)
            R[i][j] = U[i][0] * V[j][0] + U[i][1] * V[j][1] + d3 * U[i][2] * V[j][2];

    double tt[3];
#pragma unroll
    for (int i = 0; i < 3; i++)
        tt[i] = R[i][0] * mum[0] + R[i][1] * mum[1] + R[i][2] * mum[2] - muy[i];

    double T[4][4];
#pragma unroll
    for (int i = 0; i < 3; i++) {
#pragma unroll
        for (int j = 0; j < 3; j++) T[i][j] = R[i][j];
        T[i][3] = -tt[i];
    }
    T[3][0] = 0.0; T[3][1] = 0.0; T[3][2] = 0.0; T[3][3] = 1.0;

    double Tsv[4][4];
#pragma unroll
    for (int i = 0; i < 4; i++)
#pragma unroll
        for (int j = 0; j < 4; j++) Tsv[i][j] = (double)tsv_in[i * 4 + j];

    double Tinv[4][4];
#pragma unroll
    for (int i = 0; i < 3; i++) {
#pragma unroll
        for (int j = 0; j < 3; j++) Tinv[i][j] = Tsv[j][i];
        Tinv[i][3] = -(Tsv[0][i] * Tsv[0][3] + Tsv[1][i] * Tsv[1][3] + Tsv[2][i] * Tsv[2][3]);
    }
    Tinv[3][0] = 0.0; Tinv[3][1] = 0.0; Tinv[3][2] = 0.0; Tinv[3][3] = 1.0;

    double M1[4][4];
#pragma unroll
    for (int i = 0; i < 4; i++)
#pragma unroll
        for (int j = 0; j < 4; j++) {
            double t = 0.0;
#pragma unroll
            for (int k = 0; k < 4; k++) t += Tinv[i][k] * T[k][j];
            M1[i][j] = t;
        }
    float* ob = tout + b * 16;
#pragma unroll
    for (int i = 0; i < 4; i++)
#pragma unroll
        for (int j = 0; j < 4; j++) {
            double t = 0.0;
#pragma unroll
            for (int k = 0; k < 4; k++) t += M1[i][k] * Tsv[k][j];
            ob[i * 4 + j] = (float)t;
        }
}

// ---------------------------------------------------------------------------
// Stage 3: fill SCALED Q (B,13,13) into d_out. One block per batch.
// ---------------------------------------------------------------------------
__device__ __forceinline__ int sym6(int a, int c) {
    if (a > c) { int t = a; a = c; c = t; }
    return (a == 0) ? c : (a == 1) ? (2 + c) : 5;
}

__global__ __launch_bounds__(192) void q_kernel(float* __restrict__ qout)
{
    int b = blockIdx.x;
    int t = threadIdx.x;
    __shared__ float ss[NSUM];
    __shared__ float sinv;
    if (t < NSUM) ss[t] = g_sums[b * NSUM + t];
    if (t == NSUM) sinv = g_inv_scale;
    __syncthreads();

    if (t < 169) {
        float val = 0.f;
        int i = t / 13, j = t % 13;
        if (i == 0 && j == 0) {
            val = 0.f;
        } else if (i == 0 && j <= 9) {
            val = -ss[6 + (j - 1)];
        } else if (i == 0) {
            val = ss[18 + (j - 10)];
        } else if (j == 0 && i <= 9) {
            val = -ss[6 + (i - 1)];
        } else if (j == 0) {
            val = ss[18 + (i - 10)];
        } else if (i <= 9 && j <= 9) {
            int a = (i - 1) / 3, r = (i - 1) % 3;
            int bb = (j - 1) / 3, c = (j - 1) % 3;
            if (r == c) val = ss[sym6(a, bb)];
        } else if (i <= 9) {
            int a = (i - 1) / 3, r = (i - 1) % 3, c = j - 10;
            if (r == c) val = -ss[15 + a];
        } else if (j <= 9) {
            int a = (j - 1) / 3, r = (j - 1) % 3, c = i - 10;
            if (r == c) val = -ss[15 + a];
        } else {
            if (i == j) val = ss[21];
        }
        qout[b * 169 + t] = val * sinv;
    }
}

// ---------------------------------------------------------------------------
extern "C" void kernel_launch(void* const* d_in, const int* in_sizes, int n_in,
                              void* d_out, int out_size)
{
    const float* src = (const float*)d_in[0];
    const float* trg = (const float*)d_in[1];
    const float* w   = (const float*)d_in[2];
    const float* tsv = (const float*)d_in[3];
    float* out  = (float*)d_out;
    float* tout = out;                 // (B,4,4) = 4096 floats
    float* qout = out + BB * 16;       // (B,13,13) = 43264 floats

    reduce_kernel<<<BB, 256>>>(src, trg, w);
    pose_kernel<<<1, 256>>>(tsv, tout);
    q_kernel<<<BB, 192>>>(qout);
}